// round 7
// baseline (speedup 1.0000x reference)
#include <cuda_runtime.h>
#include <cstdint>

#define DM 512
#define NSH 8
#define KN 64
#define BN 2048
#define NQ 64

typedef unsigned long long ull;
__device__ __forceinline__ ull pk2(float lo, float hi) {
    ull r; asm("mov.b64 %0,{%1,%2};" : "=l"(r) : "f"(lo), "f"(hi)); return r;
}
__device__ __forceinline__ void fma2(ull& a, ull x, ull y) {
    asm("fma.rn.f32x2 %0,%1,%2,%0;" : "+l"(a) : "l"(x), "l"(y));
}
__device__ __forceinline__ ull add2(ull a, ull b) {
    ull r; asm("add.rn.f32x2 %0,%1,%2;" : "=l"(r) : "l"(a), "l"(b)); return r;
}
__device__ __forceinline__ float2 up2(ull v) {
    float2 f; asm("mov.b64 {%0,%1},%2;" : "=f"(f.x), "=f"(f.y) : "l"(v)); return f;
}

// ---------------- persistent device scratch ----------------
__device__ float g_Q[NSH * DM];
__device__ float g_qb[NQ];
__device__ float g_QKT[DM * NQ];                // [d][qi]
__device__ float g_A[(size_t)BN * NQ * DM];     // 268 MB
__device__ float g_ctx[(size_t)BN * NSH * DM];  // 33.5 MB
__device__ int   g_anyv[BN];

// ---------------- precompute ----------------
__global__ void pre_q(const float* __restrict__ shift, const float* __restrict__ Wq,
                      const float* __restrict__ bq) {
    int s = blockIdx.x, j = threadIdx.x;
    const float* sr = shift + s * DM;
    const float* wr = Wq + j * DM;
    float acc = 0.f;
    for (int d = 0; d < DM; d++) acc += sr[d] * wr[d];
    g_Q[s * DM + j] = acc + bq[j];
}

__global__ void pre_qk(const float* __restrict__ Wk, const float* __restrict__ bk) {
    int qi = blockIdx.x, d = threadIdx.x;
    int s = qi >> 3, h = qi & 7;
    const float* qrow = g_Q + s * DM + h * 64;
    float acc = 0.f;
    for (int hd = 0; hd < 64; hd++) acc += qrow[hd] * Wk[(h * 64 + hd) * DM + d];
    g_QKT[d * NQ + qi] = acc;
    if (d == 0) {
        float qb = 0.f;
        for (int hd = 0; hd < 64; hd++) qb += qrow[hd] * bk[h * 64 + hd];
        g_qb[qi] = qb;
    }
}

// ---------------- kernel A ----------------
// enc smem layout: [k][d], 16B-granule XOR swizzle: granule' = granule ^ ((k>>3)&7)
struct SmA {
    float enc[64 * 512];
    float qk[64][68];     // staged QKT chunk [d_local][qi]
    float attn[64][68];   // logits [qi][k]
    float attnT[64][68];  // probs [k][qi]
    float dist[64];
    int   valid[64];
};

__global__ __launch_bounds__(256, 1)
void kA(const float* __restrict__ enc, const int* __restrict__ valid,
        const float* __restrict__ dist, const float* __restrict__ cosp) {
    extern __shared__ char raw[];
    SmA& sm = *reinterpret_cast<SmA*>(raw);
    const int t = threadIdx.x, b = blockIdx.x;
    const int w5 = t >> 5, l = t & 31;

    // ---- P0: stage enc[b] with swizzle ----
    const float4* eb = reinterpret_cast<const float4*>(enc + (size_t)b * KN * DM);
    #pragma unroll
    for (int i = 0; i < 32; i++) {
        int idx = t + i * 256;
        float4 v = eb[idx];
        int k = idx >> 7;
        int d = (idx & 127) << 2;
        int off = d ^ (((k >> 3) & 7) << 2);
        *reinterpret_cast<float4*>(&sm.enc[k * 512 + off]) = v;
    }
    if (t < 64) { sm.dist[t] = dist[b * 64 + t]; sm.valid[t] = valid[b * 64 + t]; }
    int anyv = __syncthreads_or((t < 64) ? sm.valid[t] : 0);
    if (t == 0) g_anyv[b] = anyv;
    const float cs = cosp[0];

    // ---- P1: logits. thread tile 8k x 8q, 4-way d-split (granule-interleaved) ----
    {
        const int ds = l >> 3, sub = l & 7;
        const int q0 = w5 * 8;      // q-group = warp
        const int kg = sub;         // k-group = sub-lane
        const int k0 = kg * 8;
        ull acc[8][4];
        #pragma unroll
        for (int kk = 0; kk < 8; kk++)
            #pragma unroll
            for (int p = 0; p < 4; p++) acc[kk][p] = 0ull;

        for (int c = 0; c < 8; c++) {
            __syncthreads();
            {   // stage qk chunk [64 d][64 q]
                int dl = t >> 2, qq = (t & 3) * 16;
                #pragma unroll
                for (int u = 0; u < 4; u++)
                    *reinterpret_cast<float4*>(&sm.qk[dl][qq + u * 4]) =
                        *reinterpret_cast<const float4*>(&g_QKT[(c * 64 + dl) * 64 + qq + u * 4]);
            }
            __syncthreads();
            #pragma unroll
            for (int i = 0; i < 4; i++) {
                const int g = i * 4 + ds;       // granule within chunk (interleaved split)
                const int dl = g * 4;           // d_local, 4-aligned
                float4 e[8];
                #pragma unroll
                for (int kk = 0; kk < 8; kk++) {
                    int addr = (k0 + kk) * 512 + ((c * 64 + dl) ^ (kg << 2));
                    e[kk] = *reinterpret_cast<const float4*>(&sm.enc[addr]);
                }
                #pragma unroll
                for (int j = 0; j < 4; j++) {
                    ulonglong2 qa = *reinterpret_cast<const ulonglong2*>(&sm.qk[dl + j][q0]);
                    ulonglong2 qb2 = *reinterpret_cast<const ulonglong2*>(&sm.qk[dl + j][q0 + 4]);
                    #pragma unroll
                    for (int kk = 0; kk < 8; kk++) {
                        float ev = reinterpret_cast<const float*>(&e[kk])[j];
                        ull ebc = pk2(ev, ev);
                        fma2(acc[kk][0], ebc, qa.x);
                        fma2(acc[kk][1], ebc, qa.y);
                        fma2(acc[kk][2], ebc, qb2.x);
                        fma2(acc[kk][3], ebc, qb2.y);
                    }
                }
            }
        }
        // reduce over ds (lane xor 8, 16)
        #pragma unroll
        for (int kk = 0; kk < 8; kk++)
            #pragma unroll
            for (int p = 0; p < 4; p++) {
                acc[kk][p] = add2(acc[kk][p], __shfl_xor_sync(0xffffffffu, acc[kk][p], 8));
                acc[kk][p] = add2(acc[kk][p], __shfl_xor_sync(0xffffffffu, acc[kk][p], 16));
            }
        if (l < 8) {
            float4 qbv0 = *reinterpret_cast<const float4*>(&g_qb[q0]);
            float4 qbv1 = *reinterpret_cast<const float4*>(&g_qb[q0 + 4]);
            float qb8[8] = {qbv0.x, qbv0.y, qbv0.z, qbv0.w, qbv1.x, qbv1.y, qbv1.z, qbv1.w};
            #pragma unroll
            for (int kk = 0; kk < 8; kk++) {
                int k = l * 8 + kk;
                float dv = sm.dist[k] * cs;
                bool ok = (sm.valid[k] != 0);
                #pragma unroll
                for (int p = 0; p < 4; p++) {
                    float2 v = up2(acc[kk][p]);
                    sm.attn[q0 + 2 * p][k]     = ok ? (v.x + qb8[2 * p]) * 0.125f + dv : -10000.f;
                    sm.attn[q0 + 2 * p + 1][k] = ok ? (v.y + qb8[2 * p + 1]) * 0.125f + dv : -10000.f;
                }
            }
        }
    }
    __syncthreads();

    // ---- P2: softmax, rows spread across all warps (lane<8 each) ----
    if (l < 8) {
        int qi = w5 * 8 + l;
        float mx = -1e30f;
        #pragma unroll 8
        for (int k = 0; k < 64; k++) mx = fmaxf(mx, sm.attn[qi][k]);
        float sum = 0.f;
        #pragma unroll 8
        for (int k = 0; k < 64; k++) {
            float e = expf(sm.attn[qi][k] - mx);
            sm.attnT[k][qi] = e;
            sum += e;
        }
        float inv = 1.0f / sum;
        #pragma unroll 8
        for (int k = 0; k < 64; k++) sm.attnT[k][qi] *= inv;
    }
    __syncthreads();

    // ---- P3: A[q][d] = sum_k attnT[k][q]*enc[k][d]; tile 8q x 16d ----
    {
        const int qg = t >> 5, dg = t & 31;
        const int q0 = qg * 8, d0 = dg * 16;
        ull a[8][8];
        #pragma unroll
        for (int q = 0; q < 8; q++)
            #pragma unroll
            for (int i = 0; i < 8; i++) a[q][i] = 0ull;
        #pragma unroll 2
        for (int k = 0; k < 64; k++) {
            float4 p0 = *reinterpret_cast<const float4*>(&sm.attnT[k][q0]);
            float4 p1 = *reinterpret_cast<const float4*>(&sm.attnT[k][q0 + 4]);
            ull aq[8] = {pk2(p0.x, p0.x), pk2(p0.y, p0.y), pk2(p0.z, p0.z), pk2(p0.w, p0.w),
                         pk2(p1.x, p1.x), pk2(p1.y, p1.y), pk2(p1.z, p1.z), pk2(p1.w, p1.w)};
            const int sw = ((k >> 3) & 7) << 2;
            #pragma unroll
            for (int i = 0; i < 4; i++) {
                ulonglong2 ev = *reinterpret_cast<const ulonglong2*>(
                    &sm.enc[k * 512 + ((d0 + i * 4) ^ sw)]);
                #pragma unroll
                for (int q = 0; q < 8; q++) {
                    fma2(a[q][i * 2], aq[q], ev.x);
                    fma2(a[q][i * 2 + 1], aq[q], ev.y);
                }
            }
        }
        #pragma unroll
        for (int q = 0; q < 8; q++) {
            float* Ar = g_A + ((size_t)b * 64 + q0 + q) * 512 + d0;
            #pragma unroll
            for (int i = 0; i < 4; i++) {
                float2 lo = up2(a[q][i * 2]), hi = up2(a[q][i * 2 + 1]);
                *reinterpret_cast<float4*>(&Ar[i * 4]) = make_float4(lo.x, lo.y, hi.x, hi.y);
            }
        }
    }
}

// ---------------- kernel B1: ctx = A @ Wv^T + bv; 256 rows x 64 cols per block ----------------
__global__ __launch_bounds__(256, 2)
void kB1(const float* __restrict__ Wv, const float* __restrict__ bv) {
    __shared__ float AsT[32][260];
    __shared__ float Bs[32][68];
    const int t = threadIdx.x;
    const int r0blk = blockIdx.x * 256, h = blockIdx.y;
    const int rg = t >> 3, jg = t & 7;
    const int r0 = rg * 8, j0 = jg * 8;
    ull acc[8][4];
    #pragma unroll
    for (int i = 0; i < 8; i++)
        #pragma unroll
        for (int p = 0; p < 4; p++) acc[i][p] = 0ull;

    const size_t arow = ((size_t)(r0blk + t) * 8 + h) * 512;
    const int jB = t >> 2, khB = (t & 3) * 8;
    const size_t brow = ((size_t)(h * 64 + jB)) * 512;

    for (int kb = 0; kb < 512; kb += 32) {
        __syncthreads();
        #pragma unroll
        for (int u = 0; u < 8; u++) {
            float4 v = *reinterpret_cast<const float4*>(&g_A[arow + kb + u * 4]);
            AsT[u * 4 + 0][t] = v.x; AsT[u * 4 + 1][t] = v.y;
            AsT[u * 4 + 2][t] = v.z; AsT[u * 4 + 3][t] = v.w;
        }
        #pragma unroll
        for (int u = 0; u < 2; u++) {
            float4 v = *reinterpret_cast<const float4*>(&Wv[brow + kb + khB + u * 4]);
            Bs[khB + u * 4 + 0][jB] = v.x; Bs[khB + u * 4 + 1][jB] = v.y;
            Bs[khB + u * 4 + 2][jB] = v.z; Bs[khB + u * 4 + 3][jB] = v.w;
        }
        __syncthreads();
        #pragma unroll 8
        for (int kl = 0; kl < 32; kl++) {
            float4 aA = *reinterpret_cast<const float4*>(&AsT[kl][r0]);
            float4 aB = *reinterpret_cast<const float4*>(&AsT[kl][r0 + 4]);
            ulonglong2 b0 = *reinterpret_cast<const ulonglong2*>(&Bs[kl][j0]);
            ulonglong2 b1 = *reinterpret_cast<const ulonglong2*>(&Bs[kl][j0 + 4]);
            float av[8] = {aA.x, aA.y, aA.z, aA.w, aB.x, aB.y, aB.z, aB.w};
            #pragma unroll
            for (int rr = 0; rr < 8; rr++) {
                ull ap = pk2(av[rr], av[rr]);
                fma2(acc[rr][0], ap, b0.x); fma2(acc[rr][1], ap, b0.y);
                fma2(acc[rr][2], ap, b1.x); fma2(acc[rr][3], ap, b1.y);
            }
        }
    }
    float4 bv0 = *reinterpret_cast<const float4*>(&bv[h * 64 + j0]);
    float4 bv1 = *reinterpret_cast<const float4*>(&bv[h * 64 + j0 + 4]);
    #pragma unroll
    for (int rr = 0; rr < 8; rr++) {
        float* cr = g_ctx + ((size_t)(r0blk + r0 + rr)) * 512 + h * 64 + j0;
        float2 a0 = up2(acc[rr][0]), a1 = up2(acc[rr][1]);
        float2 a2 = up2(acc[rr][2]), a3 = up2(acc[rr][3]);
        *reinterpret_cast<float4*>(&cr[0]) =
            make_float4(a0.x + bv0.x, a0.y + bv0.y, a1.x + bv0.z, a1.y + bv0.w);
        *reinterpret_cast<float4*>(&cr[4]) =
            make_float4(a2.x + bv1.x, a2.y + bv1.y, a3.x + bv1.z, a3.y + bv1.w);
    }
}

// ---------------- kernel B2: x = ctx @ Wo^T + bo + shift, LN, mask; 32 rows/block ----------------
__global__ __launch_bounds__(256)
void kB2(const float* __restrict__ Wo, const float* __restrict__ bo,
         const float* __restrict__ shift, const float* __restrict__ lnw,
         const float* __restrict__ lnb, float* __restrict__ out) {
    __shared__ float Bs[16][516];
    __shared__ float AsT[16][36];
    __shared__ float red[8][8][2];
    __shared__ float muS[32], rsS[32];
    const int t = threadIdx.x;
    const int row0 = blockIdx.x * 32;
    const int rg = t >> 6, eg = t & 63;
    const int r0 = rg * 8, e0 = eg * 8;
    ull acc[8][4];
    #pragma unroll
    for (int i = 0; i < 8; i++)
        #pragma unroll
        for (int p = 0; p < 4; p++) acc[i][p] = 0ull;

    const int eS = t * 2;

    for (int kb = 0; kb < 512; kb += 16) {
        __syncthreads();
        #pragma unroll
        for (int ee = 0; ee < 2; ee++) {
            int e = eS + ee;
            #pragma unroll
            for (int u = 0; u < 4; u++) {
                float4 v = *reinterpret_cast<const float4*>(&Wo[(size_t)e * 512 + kb + u * 4]);
                Bs[u * 4 + 0][e] = v.x; Bs[u * 4 + 1][e] = v.y;
                Bs[u * 4 + 2][e] = v.z; Bs[u * 4 + 3][e] = v.w;
            }
        }
        if (t < 128) {
            int r = t >> 2, ks = (t & 3) * 4;
            float4 v = *reinterpret_cast<const float4*>(&g_ctx[((size_t)(row0 + r)) * 512 + kb + ks]);
            AsT[ks + 0][r] = v.x; AsT[ks + 1][r] = v.y;
            AsT[ks + 2][r] = v.z; AsT[ks + 3][r] = v.w;
        }
        __syncthreads();
        #pragma unroll 4
        for (int kl = 0; kl < 16; kl++) {
            float4 aA = *reinterpret_cast<const float4*>(&AsT[kl][r0]);
            float4 aB = *reinterpret_cast<const float4*>(&AsT[kl][r0 + 4]);
            ulonglong2 b0 = *reinterpret_cast<const ulonglong2*>(&Bs[kl][e0]);
            ulonglong2 b1 = *reinterpret_cast<const ulonglong2*>(&Bs[kl][e0 + 4]);
            float av[8] = {aA.x, aA.y, aA.z, aA.w, aB.x, aB.y, aB.z, aB.w};
            #pragma unroll
            for (int rr = 0; rr < 8; rr++) {
                ull ap = pk2(av[rr], av[rr]);
                fma2(acc[rr][0], ap, b0.x); fma2(acc[rr][1], ap, b0.y);
                fma2(acc[rr][2], ap, b1.x); fma2(acc[rr][3], ap, b1.y);
            }
        }
    }

    // epilogue
    const int w = t >> 5, lane = t & 31;
    float x[8][8], p[8], q[8];
    float4 bo0 = *reinterpret_cast<const float4*>(&bo[e0]);
    float4 bo1 = *reinterpret_cast<const float4*>(&bo[e0 + 4]);
    float bov[8] = {bo0.x, bo0.y, bo0.z, bo0.w, bo1.x, bo1.y, bo1.z, bo1.w};
    #pragma unroll
    for (int rr = 0; rr < 8; rr++) {
        int row = row0 + r0 + rr;
        int s = row & 7;
        float4 s0 = *reinterpret_cast<const float4*>(&shift[s * 512 + e0]);
        float4 s1 = *reinterpret_cast<const float4*>(&shift[s * 512 + e0 + 4]);
        float sh[8] = {s0.x, s0.y, s0.z, s0.w, s1.x, s1.y, s1.z, s1.w};
        float2 a0 = up2(acc[rr][0]), a1 = up2(acc[rr][1]);
        float2 a2 = up2(acc[rr][2]), a3 = up2(acc[rr][3]);
        float xv[8] = {a0.x, a0.y, a1.x, a1.y, a2.x, a2.y, a3.x, a3.y};
        p[rr] = 0.f; q[rr] = 0.f;
        #pragma unroll
        for (int e = 0; e < 8; e++) {
            float val = xv[e] + bov[e] + sh[e];
            x[rr][e] = val;
            p[rr] += val;
            q[rr] += val * val;
        }
    }
    #pragma unroll
    for (int rr = 0; rr < 8; rr++) {
        #pragma unroll
        for (int off = 16; off; off >>= 1) {
            p[rr] += __shfl_xor_sync(0xffffffffu, p[rr], off);
            q[rr] += __shfl_xor_sync(0xffffffffu, q[rr], off);
        }
    }
    if (lane == 0) {
        #pragma unroll
        for (int rr = 0; rr < 8; rr++) { red[w][rr][0] = p[rr]; red[w][rr][1] = q[rr]; }
    }
    __syncthreads();
    if (t < 32) {
        int rgs = t >> 3, rr = t & 7;
        float S = red[rgs * 2][rr][0] + red[rgs * 2 + 1][rr][0];
        float Q2 = red[rgs * 2][rr][1] + red[rgs * 2 + 1][rr][1];
        float m = S * (1.0f / 512.0f);
        float var = Q2 * (1.0f / 512.0f) - m * m;
        muS[t] = m;
        rsS[t] = rsqrtf(var + 1e-5f);
    }
    __syncthreads();
    float4 lw0 = *reinterpret_cast<const float4*>(&lnw[e0]);
    float4 lw1 = *reinterpret_cast<const float4*>(&lnw[e0 + 4]);
    float4 lb0 = *reinterpret_cast<const float4*>(&lnb[e0]);
    float4 lb1 = *reinterpret_cast<const float4*>(&lnb[e0 + 4]);
    float lwv[8] = {lw0.x, lw0.y, lw0.z, lw0.w, lw1.x, lw1.y, lw1.z, lw1.w};
    float lbv[8] = {lb0.x, lb0.y, lb0.z, lb0.w, lb1.x, lb1.y, lb1.z, lb1.w};
    #pragma unroll
    for (int rr = 0; rr < 8; rr++) {
        int row = row0 + r0 + rr;
        float av = g_anyv[row >> 3] ? 1.0f : 0.0f;
        float m = muS[r0 + rr], rs = rsS[r0 + rr];
        float o[8];
        #pragma unroll
        for (int e = 0; e < 8; e++)
            o[e] = ((x[rr][e] - m) * rs * lwv[e] + lbv[e]) * av;
        *reinterpret_cast<float4*>(&out[(size_t)row * 512 + e0]) =
            make_float4(o[0], o[1], o[2], o[3]);
        *reinterpret_cast<float4*>(&out[(size_t)row * 512 + e0 + 4]) =
            make_float4(o[4], o[5], o[6], o[7]);
    }
}

// ---------------- launch ----------------
extern "C" void kernel_launch(void* const* d_in, const int* in_sizes, int n_in,
                              void* d_out, int out_size) {
    const float* enc   = (const float*)d_in[0];
    const int*   valid = (const int*)d_in[1];
    const float* dist  = (const float*)d_in[2];
    const float* shift = (const float*)d_in[3];
    const float* Wq    = (const float*)d_in[4];
    const float* bq    = (const float*)d_in[5];
    const float* Wk    = (const float*)d_in[6];
    const float* bk    = (const float*)d_in[7];
    const float* Wv    = (const float*)d_in[8];
    const float* bv    = (const float*)d_in[9];
    const float* Wo    = (const float*)d_in[10];
    const float* bo    = (const float*)d_in[11];
    const float* lnw   = (const float*)d_in[12];
    const float* lnb   = (const float*)d_in[13];
    const float* cosp  = (const float*)d_in[14];
    float* out = (float*)d_out;

    pre_q<<<NSH, DM>>>(shift, Wq, bq);
    pre_qk<<<NQ, DM>>>(Wk, bk);

    int smemA = (int)sizeof(SmA);
    cudaFuncSetAttribute(kA, cudaFuncAttributeMaxDynamicSharedMemorySize, smemA);
    kA<<<BN, 256, smemA>>>(enc, valid, dist, cosp);

    dim3 gB1(64, 8);
    kB1<<<gB1, 256>>>(Wv, bv);

    kB2<<<512, 256>>>(Wo, bo, shift, lnw, lnb, out);
}